// round 9
// baseline (speedup 1.0000x reference)
#include <cuda_runtime.h>
#include <cstdint>

// Problem constants (SGC_77584289235646): fixed shapes.
#define IN_DIM    128
#define EMB_DIM   32
#define MAX_NODES 100000
#define MAX_EDGES 1600000
#define SCAN_B    1024
#define MAX_SCAN_BLOCKS 128
#define CHUNK     16            // edges per 8-thread group in the hop
#define BATCH     8             // gather batch (MLP) within a chunk

// Scratch (no cudaMalloc allowed).
__device__ __align__(16) float g_hA[(size_t)MAX_NODES * EMB_DIM];
__device__ __align__(16) float g_hB[(size_t)MAX_NODES * EMB_DIM];
__device__ __align__(16) float g_hC[(size_t)MAX_NODES * EMB_DIM];
__device__ int  g_counts [MAX_NODES];
__device__ int  g_offsets[MAX_NODES];
__device__ int  g_cursor [MAX_NODES];
__device__ int  g_spine  [MAX_SCAN_BLOCKS];
__device__ volatile int g_sflag[MAX_SCAN_BLOCKS];
__device__ __align__(16) int4 g_edge[MAX_EDGES];   // {src, w-bits, dst, 0} sorted by dst

// ---------------------------------------------------------------------------
// Kernel 1: h0 = relu(x @ W^T + b). Thread-per-node, 32 accumulators,
// W staged in smem (broadcast LDS.128). FFMA-bound (~25us).
// ---------------------------------------------------------------------------
__global__ void __launch_bounds__(256)
sgc_transform(const float* __restrict__ x,
              const float* __restrict__ W,
              const float* __restrict__ b,
              float* __restrict__ h,
              int n_nodes)
{
    __shared__ float4 Ws[EMB_DIM * (IN_DIM / 4)];   // 16KB
    __shared__ float  bsh[EMB_DIM];

    for (int i = threadIdx.x; i < EMB_DIM * (IN_DIM / 4); i += blockDim.x)
        Ws[i] = reinterpret_cast<const float4*>(W)[i];
    if (threadIdx.x < EMB_DIM) bsh[threadIdx.x] = b[threadIdx.x];
    __syncthreads();

    const int node = blockIdx.x * blockDim.x + threadIdx.x;
    if (node >= n_nodes) return;

    const float4* xr = reinterpret_cast<const float4*>(x + (size_t)node * IN_DIM);

    float acc[EMB_DIM];
    #pragma unroll
    for (int e = 0; e < EMB_DIM; ++e) acc[e] = 0.f;

    #pragma unroll 4
    for (int kc = 0; kc < IN_DIM / 4; ++kc) {
        const float4 xv = xr[kc];
        #pragma unroll
        for (int e = 0; e < EMB_DIM; ++e) {
            const float4 wv = Ws[e * (IN_DIM / 4) + kc];
            acc[e] = fmaf(xv.x, wv.x, acc[e]);
            acc[e] = fmaf(xv.y, wv.y, acc[e]);
            acc[e] = fmaf(xv.z, wv.z, acc[e]);
            acc[e] = fmaf(xv.w, wv.w, acc[e]);
        }
    }

    float4* hp = reinterpret_cast<float4*>(h + (size_t)node * EMB_DIM);
    #pragma unroll
    for (int e = 0; e < EMB_DIM; e += 4) {
        float4 o;
        o.x = fmaxf(acc[e + 0] + bsh[e + 0], 0.f);
        o.y = fmaxf(acc[e + 1] + bsh[e + 1], 0.f);
        o.z = fmaxf(acc[e + 2] + bsh[e + 2], 0.f);
        o.w = fmaxf(acc[e + 3] + bsh[e + 3], 0.f);
        hp[e / 4] = o;
    }
}

// ---------------------------------------------------------------------------
// CSR build: histogram (also clears spine flags) -> single-pass scan with
// spine lookback -> cursor-scatter.
// ---------------------------------------------------------------------------
__global__ void csr_histogram(const int* __restrict__ dst, int n_edges)
{
    const int gid = blockIdx.x * blockDim.x + threadIdx.x;
    if (gid < MAX_SCAN_BLOCKS) g_sflag[gid] = 0;   // ordered before scan (same stream)
    int i = gid * 4;
    if (i + 3 < n_edges) {
        const int4 d = *reinterpret_cast<const int4*>(dst + i);
        atomicAdd(&g_counts[d.x], 1);
        atomicAdd(&g_counts[d.y], 1);
        atomicAdd(&g_counts[d.z], 1);
        atomicAdd(&g_counts[d.w], 1);
    } else {
        for (; i < n_edges; ++i) atomicAdd(&g_counts[dst[i]], 1);
    }
}

// Single-pass exclusive scan: block-local shuffle scan, publish block total,
// warp0 spin-waits on all predecessors' totals (all blocks resident: grid<=128,
// 2 blocks/SM capacity at 1024 thr -> 296 slots), then add prefix.
__global__ void __launch_bounds__(SCAN_B)
csr_scan(int n)
{
    __shared__ int wsum[32];
    __shared__ int prefix;
    const int i    = blockIdx.x * SCAN_B + threadIdx.x;
    const int lane = threadIdx.x & 31;
    const int warp = threadIdx.x >> 5;

    const int v = (i < n) ? g_counts[i] : 0;
    int incl = v;
    #pragma unroll
    for (int off = 1; off < 32; off <<= 1) {
        int t = __shfl_up_sync(0xffffffffu, incl, off);
        if (lane >= off) incl += t;
    }
    if (lane == 31) wsum[warp] = incl;
    __syncthreads();

    if (warp == 0) {
        int s = wsum[lane];
        int si = s;
        #pragma unroll
        for (int off = 1; off < 32; off <<= 1) {
            int t = __shfl_up_sync(0xffffffffu, si, off);
            if (lane >= off) si += t;
        }
        wsum[lane] = si - s;                       // exclusive warp offset
        // Publish this block's total, then look back.
        if (lane == 31) {
            g_spine[blockIdx.x] = si;
            __threadfence();
            g_sflag[blockIdx.x] = 1;
        }
        int p = 0;
        for (int idx = lane; idx < (int)blockIdx.x; idx += 32) {
            while (g_sflag[idx] == 0) { }          // spin (predecessor resident)
            p += g_spine[idx];
        }
        #pragma unroll
        for (int off = 16; off > 0; off >>= 1)
            p += __shfl_down_sync(0xffffffffu, p, off);
        if (lane == 0) prefix = p;
    }
    __syncthreads();

    if (i < n) {
        const int o = incl - v + wsum[warp] + prefix;
        g_offsets[i] = o;
        g_cursor[i]  = o;
    }
}

__global__ void csr_scatter(const int* __restrict__ src,
                            const int* __restrict__ dst,
                            const float* __restrict__ w,
                            int n_edges)
{
    int i = (blockIdx.x * blockDim.x + threadIdx.x) * 4;
    if (i + 3 < n_edges) {
        const int4   s4 = *reinterpret_cast<const int4*>(src + i);
        const int4   d4 = *reinterpret_cast<const int4*>(dst + i);
        const float4 w4 = *reinterpret_cast<const float4*>(w + i);
        int p;
        p = atomicAdd(&g_cursor[d4.x], 1); g_edge[p] = make_int4(s4.x, __float_as_int(w4.x), d4.x, 0);
        p = atomicAdd(&g_cursor[d4.y], 1); g_edge[p] = make_int4(s4.y, __float_as_int(w4.y), d4.y, 0);
        p = atomicAdd(&g_cursor[d4.z], 1); g_edge[p] = make_int4(s4.z, __float_as_int(w4.z), d4.z, 0);
        p = atomicAdd(&g_cursor[d4.w], 1); g_edge[p] = make_int4(s4.w, __float_as_int(w4.w), d4.w, 0);
    } else {
        for (; i < n_edges; ++i) {
            int p = atomicAdd(&g_cursor[dst[i]], 1);
            g_edge[p] = make_int4(src[i], __float_as_int(w[i]), dst[i], 0);
        }
    }
}

// ---------------------------------------------------------------------------
// Kernel 2: one hop. 8-thread group owns CHUNK consecutive dst-sorted edges;
// thread c owns the c-th 16B chunk of the row. BATCH-load edge records and
// issue ALL gathers BEFORE any RED flush (the asm "memory" clobber is a
// compiler reorder barrier, so interleaved gathers would serialize: MLP ~1-2).
// This realizes MLP=8 per thread. h_out must be pre-zeroed.
// ---------------------------------------------------------------------------
__global__ void __launch_bounds__(256)
sgc_hop_chunk(const float* __restrict__ h_in,
              float* __restrict__ h_out,
              int n_edges)
{
    const int gid = blockIdx.x * blockDim.x + threadIdx.x;
    const int grp = gid >> 3;
    const int c   = gid & 7;
    const int e0  = grp * CHUNK;
    if (e0 >= n_edges) return;
    const int e1 = min(e0 + CHUNK, n_edges);

    float4 acc = make_float4(0.f, 0.f, 0.f, 0.f);
    int cur = g_edge[e0].z;

    int j = e0;
    while (j < e1) {
        const int nb = min(BATCH, e1 - j);
        float  wb[BATCH];
        int    db[BATCH];
        float4 vb[BATCH];
        // Phase 1: load edges + issue all gathers (no REDs in between).
        #pragma unroll
        for (int i = 0; i < BATCH; ++i) {
            if (i < nb) {
                const int4 ed = g_edge[j + i];
                wb[i] = __int_as_float(ed.y);
                db[i] = ed.z;
                vb[i] = __ldcg(reinterpret_cast<const float4*>(
                            h_in + (size_t)ed.x * EMB_DIM) + c);
            }
        }
        // Phase 2: accumulate with boundary flushes.
        #pragma unroll
        for (int i = 0; i < BATCH; ++i) {
            if (i < nb) {
                if (db[i] != cur) {
                    float* p = h_out + (size_t)cur * EMB_DIM + (size_t)c * 4;
                    asm volatile("red.global.add.v4.f32 [%0], {%1, %2, %3, %4};"
                                 :: "l"(p), "f"(acc.x), "f"(acc.y), "f"(acc.z), "f"(acc.w)
                                 : "memory");
                    acc = make_float4(0.f, 0.f, 0.f, 0.f);
                    cur = db[i];
                }
                acc.x = fmaf(vb[i].x, wb[i], acc.x);
                acc.y = fmaf(vb[i].y, wb[i], acc.y);
                acc.z = fmaf(vb[i].z, wb[i], acc.z);
                acc.w = fmaf(vb[i].w, wb[i], acc.w);
            }
        }
        j += nb;
    }
    float* p = h_out + (size_t)cur * EMB_DIM + (size_t)c * 4;
    asm volatile("red.global.add.v4.f32 [%0], {%1, %2, %3, %4};"
                 :: "l"(p), "f"(acc.x), "f"(acc.y), "f"(acc.z), "f"(acc.w)
                 : "memory");
}

// ---------------------------------------------------------------------------
// Launcher. Fork/join under graph capture: transform + ALL output zeroing on
// side stream, CSR build on legacy stream; join; 3 hops (no serial memsets).
// ---------------------------------------------------------------------------
extern "C" void kernel_launch(void* const* d_in, const int* in_sizes, int n_in,
                              void* d_out, int out_size)
{
    const float* x   = (const float*)d_in[0];
    const float* W   = (const float*)d_in[1];
    const float* b   = (const float*)d_in[2];
    const float* w   = (const float*)d_in[3];
    const int*   src = (const int*)d_in[4];
    const int*   dst = (const int*)d_in[5];
    float* out = (float*)d_out;

    const int n_nodes = in_sizes[0] / IN_DIM;
    const int n_edges = in_sizes[3];
    const size_t h_bytes = (size_t)n_nodes * EMB_DIM * sizeof(float);

    float* hA = nullptr; float* hB = nullptr; float* hC = nullptr; int* counts = nullptr;
    cudaGetSymbolAddress((void**)&hA, g_hA);
    cudaGetSymbolAddress((void**)&hB, g_hB);
    cudaGetSymbolAddress((void**)&hC, g_hC);
    cudaGetSymbolAddress((void**)&counts, g_counts);

    cudaStream_t s2;
    cudaEvent_t evFork, evJoin;
    cudaStreamCreateWithFlags(&s2, cudaStreamNonBlocking);
    cudaEventCreateWithFlags(&evFork, cudaEventDisableTiming);
    cudaEventCreateWithFlags(&evJoin, cudaEventDisableTiming);

    // Fork side stream off the capture-origin (legacy) stream.
    cudaEventRecord(evFork, 0);
    cudaStreamWaitEvent(s2, evFork, 0);

    // Branch A (s2): transform + zero all hop outputs.
    sgc_transform<<<(n_nodes + 255) / 256, 256, 0, s2>>>(x, W, b, hA, n_nodes);
    cudaMemsetAsync(hB, 0, h_bytes, s2);
    cudaMemsetAsync(hC, 0, h_bytes, s2);
    cudaMemsetAsync(out, 0, (size_t)out_size * sizeof(float), s2);

    // Branch B (legacy stream): CSR build.
    cudaMemsetAsync(counts, 0, (size_t)n_nodes * sizeof(int));
    csr_histogram<<<(n_edges / 4 + 255) / 256, 256>>>(dst, n_edges);
    const int scan_blocks = (n_nodes + SCAN_B - 1) / SCAN_B;
    csr_scan<<<scan_blocks, SCAN_B>>>(n_nodes);
    csr_scatter<<<(n_edges / 4 + 255) / 256, 256>>>(src, dst, w, n_edges);

    // Join.
    cudaEventRecord(evJoin, s2);
    cudaStreamWaitEvent(0, evJoin, 0);

    // 3 hops (legacy stream), no serial memsets.
    const long long n_grp = ((long long)n_edges + CHUNK - 1) / CHUNK;
    const int hop_blocks = (int)((n_grp * 8 + 255) / 256);

    sgc_hop_chunk<<<hop_blocks, 256>>>(hA, hB, n_edges);
    sgc_hop_chunk<<<hop_blocks, 256>>>(hB, hC, n_edges);
    sgc_hop_chunk<<<hop_blocks, 256>>>(hC, out, n_edges);
}

// round 10
// speedup vs baseline: 1.0325x; 1.0325x over previous
#include <cuda_runtime.h>
#include <cstdint>

// Problem constants (SGC_77584289235646): fixed shapes.
#define IN_DIM    128
#define EMB_DIM   32
#define MAX_NODES 100000
#define MAX_EDGES 1600000
#define SCAN_B    1024
#define MAX_SCAN_BLOCKS 128
#define CHUNK     16            // edges per 8-thread group in the hop
#define BATCH     8             // gather batch (MLP) within a chunk

// Scratch (no cudaMalloc allowed).
__device__ __align__(16) float g_hA[(size_t)MAX_NODES * EMB_DIM];
__device__ __align__(16) float g_hB[(size_t)MAX_NODES * EMB_DIM];
__device__ __align__(16) float g_hC[(size_t)MAX_NODES * EMB_DIM];
__device__ int  g_counts [MAX_NODES];
__device__ int  g_offsets[MAX_NODES];
__device__ int  g_cursor [MAX_NODES];
__device__ int  g_spine  [MAX_SCAN_BLOCKS];
__device__ volatile int g_sflag[MAX_SCAN_BLOCKS];
__device__ __align__(16) int4 g_edge[MAX_EDGES];   // {src, w-bits, dst, 0} sorted by dst

// ---------------------------------------------------------------------------
// Kernel 1: h0 = relu(x @ W^T + b). Thread-per-node, 32 accumulators,
// W staged in smem (broadcast LDS.128). FFMA-bound (~25us).
// ---------------------------------------------------------------------------
__global__ void __launch_bounds__(256)
sgc_transform(const float* __restrict__ x,
              const float* __restrict__ W,
              const float* __restrict__ b,
              float* __restrict__ h,
              int n_nodes)
{
    __shared__ float4 Ws[EMB_DIM * (IN_DIM / 4)];   // 16KB
    __shared__ float  bsh[EMB_DIM];

    for (int i = threadIdx.x; i < EMB_DIM * (IN_DIM / 4); i += blockDim.x)
        Ws[i] = reinterpret_cast<const float4*>(W)[i];
    if (threadIdx.x < EMB_DIM) bsh[threadIdx.x] = b[threadIdx.x];
    __syncthreads();

    const int node = blockIdx.x * blockDim.x + threadIdx.x;
    if (node >= n_nodes) return;

    const float4* xr = reinterpret_cast<const float4*>(x + (size_t)node * IN_DIM);

    float acc[EMB_DIM];
    #pragma unroll
    for (int e = 0; e < EMB_DIM; ++e) acc[e] = 0.f;

    #pragma unroll 4
    for (int kc = 0; kc < IN_DIM / 4; ++kc) {
        const float4 xv = xr[kc];
        #pragma unroll
        for (int e = 0; e < EMB_DIM; ++e) {
            const float4 wv = Ws[e * (IN_DIM / 4) + kc];
            acc[e] = fmaf(xv.x, wv.x, acc[e]);
            acc[e] = fmaf(xv.y, wv.y, acc[e]);
            acc[e] = fmaf(xv.z, wv.z, acc[e]);
            acc[e] = fmaf(xv.w, wv.w, acc[e]);
        }
    }

    float4* hp = reinterpret_cast<float4*>(h + (size_t)node * EMB_DIM);
    #pragma unroll
    for (int e = 0; e < EMB_DIM; e += 4) {
        float4 o;
        o.x = fmaxf(acc[e + 0] + bsh[e + 0], 0.f);
        o.y = fmaxf(acc[e + 1] + bsh[e + 1], 0.f);
        o.z = fmaxf(acc[e + 2] + bsh[e + 2], 0.f);
        o.w = fmaxf(acc[e + 3] + bsh[e + 3], 0.f);
        hp[e / 4] = o;
    }
}

// ---------------------------------------------------------------------------
// CSR build: histogram (also clears spine flags) -> single-pass scan with
// spine lookback -> cursor-scatter.
// ---------------------------------------------------------------------------
__global__ void csr_histogram(const int* __restrict__ dst, int n_edges)
{
    const int gid = blockIdx.x * blockDim.x + threadIdx.x;
    if (gid < MAX_SCAN_BLOCKS) g_sflag[gid] = 0;   // ordered before scan (same stream)
    int i = gid * 4;
    if (i + 3 < n_edges) {
        const int4 d = *reinterpret_cast<const int4*>(dst + i);
        atomicAdd(&g_counts[d.x], 1);
        atomicAdd(&g_counts[d.y], 1);
        atomicAdd(&g_counts[d.z], 1);
        atomicAdd(&g_counts[d.w], 1);
    } else {
        for (; i < n_edges; ++i) atomicAdd(&g_counts[dst[i]], 1);
    }
}

// Single-pass exclusive scan: block-local shuffle scan, publish block total,
// warp0 spin-waits on all predecessors' totals (all blocks resident: grid<=128,
// 2 blocks/SM capacity at 1024 thr -> 296 slots), then add prefix.
__global__ void __launch_bounds__(SCAN_B)
csr_scan(int n)
{
    __shared__ int wsum[32];
    __shared__ int prefix;
    const int i    = blockIdx.x * SCAN_B + threadIdx.x;
    const int lane = threadIdx.x & 31;
    const int warp = threadIdx.x >> 5;

    const int v = (i < n) ? g_counts[i] : 0;
    int incl = v;
    #pragma unroll
    for (int off = 1; off < 32; off <<= 1) {
        int t = __shfl_up_sync(0xffffffffu, incl, off);
        if (lane >= off) incl += t;
    }
    if (lane == 31) wsum[warp] = incl;
    __syncthreads();

    if (warp == 0) {
        int s = wsum[lane];
        int si = s;
        #pragma unroll
        for (int off = 1; off < 32; off <<= 1) {
            int t = __shfl_up_sync(0xffffffffu, si, off);
            if (lane >= off) si += t;
        }
        wsum[lane] = si - s;                       // exclusive warp offset
        // Publish this block's total, then look back.
        if (lane == 31) {
            g_spine[blockIdx.x] = si;
            __threadfence();
            g_sflag[blockIdx.x] = 1;
        }
        int p = 0;
        for (int idx = lane; idx < (int)blockIdx.x; idx += 32) {
            while (g_sflag[idx] == 0) { }          // spin (predecessor resident)
            p += g_spine[idx];
        }
        #pragma unroll
        for (int off = 16; off > 0; off >>= 1)
            p += __shfl_down_sync(0xffffffffu, p, off);
        if (lane == 0) prefix = p;
    }
    __syncthreads();

    if (i < n) {
        const int o = incl - v + wsum[warp] + prefix;
        g_offsets[i] = o;
        g_cursor[i]  = o;
    }
}

__global__ void csr_scatter(const int* __restrict__ src,
                            const int* __restrict__ dst,
                            const float* __restrict__ w,
                            int n_edges)
{
    int i = (blockIdx.x * blockDim.x + threadIdx.x) * 4;
    if (i + 3 < n_edges) {
        const int4   s4 = *reinterpret_cast<const int4*>(src + i);
        const int4   d4 = *reinterpret_cast<const int4*>(dst + i);
        const float4 w4 = *reinterpret_cast<const float4*>(w + i);
        int p;
        p = atomicAdd(&g_cursor[d4.x], 1); g_edge[p] = make_int4(s4.x, __float_as_int(w4.x), d4.x, 0);
        p = atomicAdd(&g_cursor[d4.y], 1); g_edge[p] = make_int4(s4.y, __float_as_int(w4.y), d4.y, 0);
        p = atomicAdd(&g_cursor[d4.z], 1); g_edge[p] = make_int4(s4.z, __float_as_int(w4.z), d4.z, 0);
        p = atomicAdd(&g_cursor[d4.w], 1); g_edge[p] = make_int4(s4.w, __float_as_int(w4.w), d4.w, 0);
    } else {
        for (; i < n_edges; ++i) {
            int p = atomicAdd(&g_cursor[dst[i]], 1);
            g_edge[p] = make_int4(src[i], __float_as_int(w[i]), dst[i], 0);
        }
    }
}

// ---------------------------------------------------------------------------
// Kernel 2: one hop. 8-thread group owns CHUNK consecutive dst-sorted edges;
// thread c owns the c-th 16B chunk of the row. BATCH-load edge records and
// issue ALL gathers BEFORE any RED flush (the asm "memory" clobber is a
// compiler reorder barrier, so interleaved gathers would serialize: MLP ~1-2).
// This realizes MLP=8 per thread. h_out must be pre-zeroed.
// ---------------------------------------------------------------------------
__global__ void __launch_bounds__(256)
sgc_hop_chunk(const float* __restrict__ h_in,
              float* __restrict__ h_out,
              int n_edges)
{
    const int gid = blockIdx.x * blockDim.x + threadIdx.x;
    const int grp = gid >> 3;
    const int c   = gid & 7;
    const int e0  = grp * CHUNK;
    if (e0 >= n_edges) return;
    const int e1 = min(e0 + CHUNK, n_edges);

    float4 acc = make_float4(0.f, 0.f, 0.f, 0.f);
    int cur = g_edge[e0].z;

    int j = e0;
    while (j < e1) {
        const int nb = min(BATCH, e1 - j);
        float  wb[BATCH];
        int    db[BATCH];
        float4 vb[BATCH];
        // Phase 1: load edges + issue all gathers (no REDs in between).
        #pragma unroll
        for (int i = 0; i < BATCH; ++i) {
            if (i < nb) {
                const int4 ed = g_edge[j + i];
                wb[i] = __int_as_float(ed.y);
                db[i] = ed.z;
                vb[i] = __ldcg(reinterpret_cast<const float4*>(
                            h_in + (size_t)ed.x * EMB_DIM) + c);
            }
        }
        // Phase 2: accumulate with boundary flushes.
        #pragma unroll
        for (int i = 0; i < BATCH; ++i) {
            if (i < nb) {
                if (db[i] != cur) {
                    float* p = h_out + (size_t)cur * EMB_DIM + (size_t)c * 4;
                    asm volatile("red.global.add.v4.f32 [%0], {%1, %2, %3, %4};"
                                 :: "l"(p), "f"(acc.x), "f"(acc.y), "f"(acc.z), "f"(acc.w)
                                 : "memory");
                    acc = make_float4(0.f, 0.f, 0.f, 0.f);
                    cur = db[i];
                }
                acc.x = fmaf(vb[i].x, wb[i], acc.x);
                acc.y = fmaf(vb[i].y, wb[i], acc.y);
                acc.z = fmaf(vb[i].z, wb[i], acc.z);
                acc.w = fmaf(vb[i].w, wb[i], acc.w);
            }
        }
        j += nb;
    }
    float* p = h_out + (size_t)cur * EMB_DIM + (size_t)c * 4;
    asm volatile("red.global.add.v4.f32 [%0], {%1, %2, %3, %4};"
                 :: "l"(p), "f"(acc.x), "f"(acc.y), "f"(acc.z), "f"(acc.w)
                 : "memory");
}

// ---------------------------------------------------------------------------
// Launcher. Fork/join under graph capture: transform + ALL output zeroing on
// side stream, CSR build on legacy stream; join; 3 hops (no serial memsets).
// ---------------------------------------------------------------------------
extern "C" void kernel_launch(void* const* d_in, const int* in_sizes, int n_in,
                              void* d_out, int out_size)
{
    const float* x   = (const float*)d_in[0];
    const float* W   = (const float*)d_in[1];
    const float* b   = (const float*)d_in[2];
    const float* w   = (const float*)d_in[3];
    const int*   src = (const int*)d_in[4];
    const int*   dst = (const int*)d_in[5];
    float* out = (float*)d_out;

    const int n_nodes = in_sizes[0] / IN_DIM;
    const int n_edges = in_sizes[3];
    const size_t h_bytes = (size_t)n_nodes * EMB_DIM * sizeof(float);

    float* hA = nullptr; float* hB = nullptr; float* hC = nullptr; int* counts = nullptr;
    cudaGetSymbolAddress((void**)&hA, g_hA);
    cudaGetSymbolAddress((void**)&hB, g_hB);
    cudaGetSymbolAddress((void**)&hC, g_hC);
    cudaGetSymbolAddress((void**)&counts, g_counts);

    cudaStream_t s2;
    cudaEvent_t evFork, evJoin;
    cudaStreamCreateWithFlags(&s2, cudaStreamNonBlocking);
    cudaEventCreateWithFlags(&evFork, cudaEventDisableTiming);
    cudaEventCreateWithFlags(&evJoin, cudaEventDisableTiming);

    // Fork side stream off the capture-origin (legacy) stream.
    cudaEventRecord(evFork, 0);
    cudaStreamWaitEvent(s2, evFork, 0);

    // Branch A (s2): transform + zero all hop outputs.
    sgc_transform<<<(n_nodes + 255) / 256, 256, 0, s2>>>(x, W, b, hA, n_nodes);
    cudaMemsetAsync(hB, 0, h_bytes, s2);
    cudaMemsetAsync(hC, 0, h_bytes, s2);
    cudaMemsetAsync(out, 0, (size_t)out_size * sizeof(float), s2);

    // Branch B (legacy stream): CSR build.
    cudaMemsetAsync(counts, 0, (size_t)n_nodes * sizeof(int));
    csr_histogram<<<(n_edges / 4 + 255) / 256, 256>>>(dst, n_edges);
    const int scan_blocks = (n_nodes + SCAN_B - 1) / SCAN_B;
    csr_scan<<<scan_blocks, SCAN_B>>>(n_nodes);
    csr_scatter<<<(n_edges / 4 + 255) / 256, 256>>>(src, dst, w, n_edges);

    // Join.
    cudaEventRecord(evJoin, s2);
    cudaStreamWaitEvent(0, evJoin, 0);

    // 3 hops (legacy stream), no serial memsets.
    const long long n_grp = ((long long)n_edges + CHUNK - 1) / CHUNK;
    const int hop_blocks = (int)((n_grp * 8 + 255) / 256);

    sgc_hop_chunk<<<hop_blocks, 256>>>(hA, hB, n_edges);
    sgc_hop_chunk<<<hop_blocks, 256>>>(hB, hC, n_edges);
    sgc_hop_chunk<<<hop_blocks, 256>>>(hC, out, n_edges);
}

// round 11
// speedup vs baseline: 1.0479x; 1.0149x over previous
#include <cuda_runtime.h>
#include <cstdint>

// Problem constants (SGC_77584289235646): fixed shapes.
#define IN_DIM    128
#define EMB_DIM   32
#define MAX_NODES 100000
#define MAX_EDGES 1600000
#define SCAN_B    1024
#define MAX_SCAN_BLOCKS 128
#define CHUNK     16            // edges per 8-thread group in the hop
#define BATCH     8             // gather batch (MLP) within a chunk

// Scratch (no cudaMalloc allowed).
__device__ __align__(16) float g_hA[(size_t)MAX_NODES * EMB_DIM];
__device__ __align__(16) float g_hB[(size_t)MAX_NODES * EMB_DIM];
__device__ __align__(16) float g_hC[(size_t)MAX_NODES * EMB_DIM];
__device__ int  g_counts [MAX_NODES];
__device__ int  g_offsets[MAX_NODES];
__device__ int  g_cursor [MAX_NODES];
__device__ int  g_spine  [MAX_SCAN_BLOCKS];
__device__ volatile int g_sflag[MAX_SCAN_BLOCKS];
__device__ __align__(16) int4 g_edge[MAX_EDGES];   // {src, w-bits, dst, 0} sorted by dst

// ---------------------------------------------------------------------------
// Kernel 1: h0 = relu(x @ W^T + b). Thread-per-node, 32 accumulators,
// W staged in smem (broadcast LDS.128). FFMA-bound (~25us).
// ---------------------------------------------------------------------------
__global__ void __launch_bounds__(256)
sgc_transform(const float* __restrict__ x,
              const float* __restrict__ W,
              const float* __restrict__ b,
              float* __restrict__ h,
              int n_nodes)
{
    __shared__ float4 Ws[EMB_DIM * (IN_DIM / 4)];   // 16KB
    __shared__ float  bsh[EMB_DIM];

    for (int i = threadIdx.x; i < EMB_DIM * (IN_DIM / 4); i += blockDim.x)
        Ws[i] = reinterpret_cast<const float4*>(W)[i];
    if (threadIdx.x < EMB_DIM) bsh[threadIdx.x] = b[threadIdx.x];
    __syncthreads();

    const int node = blockIdx.x * blockDim.x + threadIdx.x;
    if (node >= n_nodes) return;

    const float4* xr = reinterpret_cast<const float4*>(x + (size_t)node * IN_DIM);

    float acc[EMB_DIM];
    #pragma unroll
    for (int e = 0; e < EMB_DIM; ++e) acc[e] = 0.f;

    #pragma unroll 4
    for (int kc = 0; kc < IN_DIM / 4; ++kc) {
        const float4 xv = xr[kc];
        #pragma unroll
        for (int e = 0; e < EMB_DIM; ++e) {
            const float4 wv = Ws[e * (IN_DIM / 4) + kc];
            acc[e] = fmaf(xv.x, wv.x, acc[e]);
            acc[e] = fmaf(xv.y, wv.y, acc[e]);
            acc[e] = fmaf(xv.z, wv.z, acc[e]);
            acc[e] = fmaf(xv.w, wv.w, acc[e]);
        }
    }

    float4* hp = reinterpret_cast<float4*>(h + (size_t)node * EMB_DIM);
    #pragma unroll
    for (int e = 0; e < EMB_DIM; e += 4) {
        float4 o;
        o.x = fmaxf(acc[e + 0] + bsh[e + 0], 0.f);
        o.y = fmaxf(acc[e + 1] + bsh[e + 1], 0.f);
        o.z = fmaxf(acc[e + 2] + bsh[e + 2], 0.f);
        o.w = fmaxf(acc[e + 3] + bsh[e + 3], 0.f);
        hp[e / 4] = o;
    }
}

// ---------------------------------------------------------------------------
// CSR build: histogram (also clears spine flags) -> single-pass scan with
// spine lookback -> cursor-scatter.
// ---------------------------------------------------------------------------
__global__ void csr_histogram(const int* __restrict__ dst, int n_edges)
{
    const int gid = blockIdx.x * blockDim.x + threadIdx.x;
    if (gid < MAX_SCAN_BLOCKS) g_sflag[gid] = 0;   // ordered before scan (same stream)
    int i = gid * 4;
    if (i + 3 < n_edges) {
        const int4 d = *reinterpret_cast<const int4*>(dst + i);
        atomicAdd(&g_counts[d.x], 1);
        atomicAdd(&g_counts[d.y], 1);
        atomicAdd(&g_counts[d.z], 1);
        atomicAdd(&g_counts[d.w], 1);
    } else {
        for (; i < n_edges; ++i) atomicAdd(&g_counts[dst[i]], 1);
    }
}

// Single-pass exclusive scan: block-local shuffle scan, publish block total,
// warp0 spin-waits on all predecessors' totals (all blocks resident: grid<=128,
// 2 blocks/SM capacity at 1024 thr -> 296 slots), then add prefix.
__global__ void __launch_bounds__(SCAN_B)
csr_scan(int n)
{
    __shared__ int wsum[32];
    __shared__ int prefix;
    const int i    = blockIdx.x * SCAN_B + threadIdx.x;
    const int lane = threadIdx.x & 31;
    const int warp = threadIdx.x >> 5;

    const int v = (i < n) ? g_counts[i] : 0;
    int incl = v;
    #pragma unroll
    for (int off = 1; off < 32; off <<= 1) {
        int t = __shfl_up_sync(0xffffffffu, incl, off);
        if (lane >= off) incl += t;
    }
    if (lane == 31) wsum[warp] = incl;
    __syncthreads();

    if (warp == 0) {
        int s = wsum[lane];
        int si = s;
        #pragma unroll
        for (int off = 1; off < 32; off <<= 1) {
            int t = __shfl_up_sync(0xffffffffu, si, off);
            if (lane >= off) si += t;
        }
        wsum[lane] = si - s;                       // exclusive warp offset
        // Publish this block's total, then look back.
        if (lane == 31) {
            g_spine[blockIdx.x] = si;
            __threadfence();
            g_sflag[blockIdx.x] = 1;
        }
        int p = 0;
        for (int idx = lane; idx < (int)blockIdx.x; idx += 32) {
            while (g_sflag[idx] == 0) { }          // spin (predecessor resident)
            p += g_spine[idx];
        }
        #pragma unroll
        for (int off = 16; off > 0; off >>= 1)
            p += __shfl_down_sync(0xffffffffu, p, off);
        if (lane == 0) prefix = p;
    }
    __syncthreads();

    if (i < n) {
        const int o = incl - v + wsum[warp] + prefix;
        g_offsets[i] = o;
        g_cursor[i]  = o;
    }
}

__global__ void csr_scatter(const int* __restrict__ src,
                            const int* __restrict__ dst,
                            const float* __restrict__ w,
                            int n_edges)
{
    int i = (blockIdx.x * blockDim.x + threadIdx.x) * 4;
    if (i + 3 < n_edges) {
        const int4   s4 = *reinterpret_cast<const int4*>(src + i);
        const int4   d4 = *reinterpret_cast<const int4*>(dst + i);
        const float4 w4 = *reinterpret_cast<const float4*>(w + i);
        int p;
        p = atomicAdd(&g_cursor[d4.x], 1); g_edge[p] = make_int4(s4.x, __float_as_int(w4.x), d4.x, 0);
        p = atomicAdd(&g_cursor[d4.y], 1); g_edge[p] = make_int4(s4.y, __float_as_int(w4.y), d4.y, 0);
        p = atomicAdd(&g_cursor[d4.z], 1); g_edge[p] = make_int4(s4.z, __float_as_int(w4.z), d4.z, 0);
        p = atomicAdd(&g_cursor[d4.w], 1); g_edge[p] = make_int4(s4.w, __float_as_int(w4.w), d4.w, 0);
    } else {
        for (; i < n_edges; ++i) {
            int p = atomicAdd(&g_cursor[dst[i]], 1);
            g_edge[p] = make_int4(src[i], __float_as_int(w[i]), dst[i], 0);
        }
    }
}

// ---------------------------------------------------------------------------
// Kernel 2: one hop. 8-thread group owns CHUNK consecutive dst-sorted edges;
// thread c owns the c-th 16B chunk of the row. BATCH-load edge records and
// issue ALL gathers BEFORE any RED flush (the asm "memory" clobber is a
// compiler reorder barrier, so interleaved gathers would serialize: MLP ~1-2).
// This realizes MLP=8 per thread. h_out must be pre-zeroed.
// ---------------------------------------------------------------------------
__global__ void __launch_bounds__(256)
sgc_hop_chunk(const float* __restrict__ h_in,
              float* __restrict__ h_out,
              int n_edges)
{
    const int gid = blockIdx.x * blockDim.x + threadIdx.x;
    const int grp = gid >> 3;
    const int c   = gid & 7;
    const int e0  = grp * CHUNK;
    if (e0 >= n_edges) return;
    const int e1 = min(e0 + CHUNK, n_edges);

    float4 acc = make_float4(0.f, 0.f, 0.f, 0.f);
    int cur = g_edge[e0].z;

    int j = e0;
    while (j < e1) {
        const int nb = min(BATCH, e1 - j);
        float  wb[BATCH];
        int    db[BATCH];
        float4 vb[BATCH];
        // Phase 1: load edges + issue all gathers (no REDs in between).
        #pragma unroll
        for (int i = 0; i < BATCH; ++i) {
            if (i < nb) {
                const int4 ed = g_edge[j + i];
                wb[i] = __int_as_float(ed.y);
                db[i] = ed.z;
                vb[i] = __ldcg(reinterpret_cast<const float4*>(
                            h_in + (size_t)ed.x * EMB_DIM) + c);
            }
        }
        // Phase 2: accumulate with boundary flushes.
        #pragma unroll
        for (int i = 0; i < BATCH; ++i) {
            if (i < nb) {
                if (db[i] != cur) {
                    float* p = h_out + (size_t)cur * EMB_DIM + (size_t)c * 4;
                    asm volatile("red.global.add.v4.f32 [%0], {%1, %2, %3, %4};"
                                 :: "l"(p), "f"(acc.x), "f"(acc.y), "f"(acc.z), "f"(acc.w)
                                 : "memory");
                    acc = make_float4(0.f, 0.f, 0.f, 0.f);
                    cur = db[i];
                }
                acc.x = fmaf(vb[i].x, wb[i], acc.x);
                acc.y = fmaf(vb[i].y, wb[i], acc.y);
                acc.z = fmaf(vb[i].z, wb[i], acc.z);
                acc.w = fmaf(vb[i].w, wb[i], acc.w);
            }
        }
        j += nb;
    }
    float* p = h_out + (size_t)cur * EMB_DIM + (size_t)c * 4;
    asm volatile("red.global.add.v4.f32 [%0], {%1, %2, %3, %4};"
                 :: "l"(p), "f"(acc.x), "f"(acc.y), "f"(acc.z), "f"(acc.w)
                 : "memory");
}

// ---------------------------------------------------------------------------
// Launcher. Fork/join under graph capture: transform + ALL output zeroing on
// side stream, CSR build on legacy stream; join; 3 hops (no serial memsets).
// ---------------------------------------------------------------------------
extern "C" void kernel_launch(void* const* d_in, const int* in_sizes, int n_in,
                              void* d_out, int out_size)
{
    const float* x   = (const float*)d_in[0];
    const float* W   = (const float*)d_in[1];
    const float* b   = (const float*)d_in[2];
    const float* w   = (const float*)d_in[3];
    const int*   src = (const int*)d_in[4];
    const int*   dst = (const int*)d_in[5];
    float* out = (float*)d_out;

    const int n_nodes = in_sizes[0] / IN_DIM;
    const int n_edges = in_sizes[3];
    const size_t h_bytes = (size_t)n_nodes * EMB_DIM * sizeof(float);

    float* hA = nullptr; float* hB = nullptr; float* hC = nullptr; int* counts = nullptr;
    cudaGetSymbolAddress((void**)&hA, g_hA);
    cudaGetSymbolAddress((void**)&hB, g_hB);
    cudaGetSymbolAddress((void**)&hC, g_hC);
    cudaGetSymbolAddress((void**)&counts, g_counts);

    cudaStream_t s2;
    cudaEvent_t evFork, evJoin;
    cudaStreamCreateWithFlags(&s2, cudaStreamNonBlocking);
    cudaEventCreateWithFlags(&evFork, cudaEventDisableTiming);
    cudaEventCreateWithFlags(&evJoin, cudaEventDisableTiming);

    // Fork side stream off the capture-origin (legacy) stream.
    cudaEventRecord(evFork, 0);
    cudaStreamWaitEvent(s2, evFork, 0);

    // Branch A (s2): transform + zero all hop outputs.
    sgc_transform<<<(n_nodes + 255) / 256, 256, 0, s2>>>(x, W, b, hA, n_nodes);
    cudaMemsetAsync(hB, 0, h_bytes, s2);
    cudaMemsetAsync(hC, 0, h_bytes, s2);
    cudaMemsetAsync(out, 0, (size_t)out_size * sizeof(float), s2);

    // Branch B (legacy stream): CSR build.
    cudaMemsetAsync(counts, 0, (size_t)n_nodes * sizeof(int));
    csr_histogram<<<(n_edges / 4 + 255) / 256, 256>>>(dst, n_edges);
    const int scan_blocks = (n_nodes + SCAN_B - 1) / SCAN_B;
    csr_scan<<<scan_blocks, SCAN_B>>>(n_nodes);
    csr_scatter<<<(n_edges / 4 + 255) / 256, 256>>>(src, dst, w, n_edges);

    // Join.
    cudaEventRecord(evJoin, s2);
    cudaStreamWaitEvent(0, evJoin, 0);

    // 3 hops (legacy stream), no serial memsets.
    const long long n_grp = ((long long)n_edges + CHUNK - 1) / CHUNK;
    const int hop_blocks = (int)((n_grp * 8 + 255) / 256);

    sgc_hop_chunk<<<hop_blocks, 256>>>(hA, hB, n_edges);
    sgc_hop_chunk<<<hop_blocks, 256>>>(hB, hC, n_edges);
    sgc_hop_chunk<<<hop_blocks, 256>>>(hC, out, n_edges);
}

// round 12
// speedup vs baseline: 1.3746x; 1.3118x over previous
#include <cuda_runtime.h>
#include <cstdint>

// Problem constants (SGC_77584289235646): fixed shapes.
#define IN_DIM    128
#define EMB_DIM   32
#define MAX_NODES 100000
#define MAX_EDGES 1600000
#define SCAN_B    1024
#define MAX_SCAN_BLOCKS 128
#define CHUNK     16            // edges per 8-thread group in the hop

// Scratch (no cudaMalloc allowed).
__device__ __align__(16) float g_hA[(size_t)MAX_NODES * EMB_DIM];
__device__ __align__(16) float g_hB[(size_t)MAX_NODES * EMB_DIM];
__device__ __align__(16) float g_hC[(size_t)MAX_NODES * EMB_DIM];
__device__ int  g_counts [MAX_NODES];
__device__ int  g_offsets[MAX_NODES];
__device__ int  g_cursor [MAX_NODES];
__device__ int  g_spine  [MAX_SCAN_BLOCKS];
__device__ volatile int g_sflag[MAX_SCAN_BLOCKS];
__device__ __align__(16) int4 g_edge[MAX_EDGES];   // {src, w-bits, dst, 0} sorted by dst

// ---------------------------------------------------------------------------
// Kernel 1: h0 = relu(x @ W^T + b). Thread-per-node, 32 accumulators,
// W staged in smem (broadcast LDS.128). FFMA-bound (~25us).
// ---------------------------------------------------------------------------
__global__ void __launch_bounds__(256)
sgc_transform(const float* __restrict__ x,
              const float* __restrict__ W,
              const float* __restrict__ b,
              float* __restrict__ h,
              int n_nodes)
{
    __shared__ float4 Ws[EMB_DIM * (IN_DIM / 4)];   // 16KB
    __shared__ float  bsh[EMB_DIM];

    for (int i = threadIdx.x; i < EMB_DIM * (IN_DIM / 4); i += blockDim.x)
        Ws[i] = reinterpret_cast<const float4*>(W)[i];
    if (threadIdx.x < EMB_DIM) bsh[threadIdx.x] = b[threadIdx.x];
    __syncthreads();

    const int node = blockIdx.x * blockDim.x + threadIdx.x;
    if (node >= n_nodes) return;

    const float4* xr = reinterpret_cast<const float4*>(x + (size_t)node * IN_DIM);

    float acc[EMB_DIM];
    #pragma unroll
    for (int e = 0; e < EMB_DIM; ++e) acc[e] = 0.f;

    #pragma unroll 4
    for (int kc = 0; kc < IN_DIM / 4; ++kc) {
        const float4 xv = xr[kc];
        #pragma unroll
        for (int e = 0; e < EMB_DIM; ++e) {
            const float4 wv = Ws[e * (IN_DIM / 4) + kc];
            acc[e] = fmaf(xv.x, wv.x, acc[e]);
            acc[e] = fmaf(xv.y, wv.y, acc[e]);
            acc[e] = fmaf(xv.z, wv.z, acc[e]);
            acc[e] = fmaf(xv.w, wv.w, acc[e]);
        }
    }

    float4* hp = reinterpret_cast<float4*>(h + (size_t)node * EMB_DIM);
    #pragma unroll
    for (int e = 0; e < EMB_DIM; e += 4) {
        float4 o;
        o.x = fmaxf(acc[e + 0] + bsh[e + 0], 0.f);
        o.y = fmaxf(acc[e + 1] + bsh[e + 1], 0.f);
        o.z = fmaxf(acc[e + 2] + bsh[e + 2], 0.f);
        o.w = fmaxf(acc[e + 3] + bsh[e + 3], 0.f);
        hp[e / 4] = o;
    }
}

// ---------------------------------------------------------------------------
// CSR build: histogram (also clears spine flags) -> single-pass lookback
// scan -> cursor-scatter. Hist/scatter process 8 edges/thread for MLP=8
// (they are atomic-latency-bound, issue% ~3).
// ---------------------------------------------------------------------------
__global__ void csr_histogram(const int* __restrict__ dst, int n_edges)
{
    const int gid = blockIdx.x * blockDim.x + threadIdx.x;
    if (gid < MAX_SCAN_BLOCKS) g_sflag[gid] = 0;   // ordered before scan (same stream)
    int i = gid * 8;
    if (i + 7 < n_edges) {
        const int4 d0 = *reinterpret_cast<const int4*>(dst + i);
        const int4 d1 = *reinterpret_cast<const int4*>(dst + i + 4);
        atomicAdd(&g_counts[d0.x], 1); atomicAdd(&g_counts[d0.y], 1);
        atomicAdd(&g_counts[d0.z], 1); atomicAdd(&g_counts[d0.w], 1);
        atomicAdd(&g_counts[d1.x], 1); atomicAdd(&g_counts[d1.y], 1);
        atomicAdd(&g_counts[d1.z], 1); atomicAdd(&g_counts[d1.w], 1);
    } else {
        for (; i < n_edges; ++i) atomicAdd(&g_counts[dst[i]], 1);
    }
}

// Single-pass exclusive scan with spine lookback (all <=128 blocks resident).
__global__ void __launch_bounds__(SCAN_B)
csr_scan(int n)
{
    __shared__ int wsum[32];
    __shared__ int prefix;
    const int i    = blockIdx.x * SCAN_B + threadIdx.x;
    const int lane = threadIdx.x & 31;
    const int warp = threadIdx.x >> 5;

    const int v = (i < n) ? g_counts[i] : 0;
    int incl = v;
    #pragma unroll
    for (int off = 1; off < 32; off <<= 1) {
        int t = __shfl_up_sync(0xffffffffu, incl, off);
        if (lane >= off) incl += t;
    }
    if (lane == 31) wsum[warp] = incl;
    __syncthreads();

    if (warp == 0) {
        int s = wsum[lane];
        int si = s;
        #pragma unroll
        for (int off = 1; off < 32; off <<= 1) {
            int t = __shfl_up_sync(0xffffffffu, si, off);
            if (lane >= off) si += t;
        }
        wsum[lane] = si - s;
        if (lane == 31) {
            g_spine[blockIdx.x] = si;
            __threadfence();
            g_sflag[blockIdx.x] = 1;
        }
        int p = 0;
        for (int idx = lane; idx < (int)blockIdx.x; idx += 32) {
            while (g_sflag[idx] == 0) { }
            p += g_spine[idx];
        }
        #pragma unroll
        for (int off = 16; off > 0; off >>= 1)
            p += __shfl_down_sync(0xffffffffu, p, off);
        if (lane == 0) prefix = p;
    }
    __syncthreads();

    if (i < n) {
        const int o = incl - v + wsum[warp] + prefix;
        g_offsets[i] = o;
        g_cursor[i]  = o;
    }
}

__global__ void csr_scatter(const int* __restrict__ src,
                            const int* __restrict__ dst,
                            const float* __restrict__ w,
                            int n_edges)
{
    int i = (blockIdx.x * blockDim.x + threadIdx.x) * 8;
    if (i + 7 < n_edges) {
        const int4   s0 = *reinterpret_cast<const int4*>(src + i);
        const int4   s1 = *reinterpret_cast<const int4*>(src + i + 4);
        const int4   d0 = *reinterpret_cast<const int4*>(dst + i);
        const int4   d1 = *reinterpret_cast<const int4*>(dst + i + 4);
        const float4 w0 = *reinterpret_cast<const float4*>(w + i);
        const float4 w1 = *reinterpret_cast<const float4*>(w + i + 4);
        // 8 independent atomicAdd chains -> MLP 8.
        int p0 = atomicAdd(&g_cursor[d0.x], 1);
        int p1 = atomicAdd(&g_cursor[d0.y], 1);
        int p2 = atomicAdd(&g_cursor[d0.z], 1);
        int p3 = atomicAdd(&g_cursor[d0.w], 1);
        int p4 = atomicAdd(&g_cursor[d1.x], 1);
        int p5 = atomicAdd(&g_cursor[d1.y], 1);
        int p6 = atomicAdd(&g_cursor[d1.z], 1);
        int p7 = atomicAdd(&g_cursor[d1.w], 1);
        g_edge[p0] = make_int4(s0.x, __float_as_int(w0.x), d0.x, 0);
        g_edge[p1] = make_int4(s0.y, __float_as_int(w0.y), d0.y, 0);
        g_edge[p2] = make_int4(s0.z, __float_as_int(w0.z), d0.z, 0);
        g_edge[p3] = make_int4(s0.w, __float_as_int(w0.w), d0.w, 0);
        g_edge[p4] = make_int4(s1.x, __float_as_int(w1.x), d1.x, 0);
        g_edge[p5] = make_int4(s1.y, __float_as_int(w1.y), d1.y, 0);
        g_edge[p6] = make_int4(s1.z, __float_as_int(w1.z), d1.z, 0);
        g_edge[p7] = make_int4(s1.w, __float_as_int(w1.w), d1.w, 0);
    } else {
        for (; i < n_edges; ++i) {
            int p = atomicAdd(&g_cursor[dst[i]], 1);
            g_edge[p] = make_int4(src[i], __float_as_int(w[i]), dst[i], 0);
        }
    }
}

// ---------------------------------------------------------------------------
// Kernel 2: one hop (lean R7 structure). 8-thread group owns CHUNK
// consecutive dst-sorted edges; thread c owns the c-th 16B row chunk.
// The RED asm has NO "memory" clobber: it only touches h_out (never read
// here), so the compiler may pipeline h_in gathers across flushes freely.
// Data deps on the "f" operands order each RED after its accumulation;
// volatile asm preserves RED-vs-RED order. h_out must be pre-zeroed.
// ---------------------------------------------------------------------------
__global__ void __launch_bounds__(256)
sgc_hop_chunk(const float* __restrict__ h_in,
              float* __restrict__ h_out,
              int n_edges)
{
    const int gid = blockIdx.x * blockDim.x + threadIdx.x;
    const int grp = gid >> 3;
    const int c   = gid & 7;
    const int e0  = grp * CHUNK;
    if (e0 >= n_edges) return;
    const int e1 = min(e0 + CHUNK, n_edges);

    float4 acc = make_float4(0.f, 0.f, 0.f, 0.f);
    int cur = g_edge[e0].z;

    #pragma unroll 4
    for (int j = e0; j < e1; ++j) {
        const int4 ed = g_edge[j];
        if (ed.z != cur) {
            float* p = h_out + (size_t)cur * EMB_DIM + (size_t)c * 4;
            asm volatile("red.global.add.v4.f32 [%0], {%1, %2, %3, %4};"
                         :: "l"(p), "f"(acc.x), "f"(acc.y), "f"(acc.z), "f"(acc.w));
            acc = make_float4(0.f, 0.f, 0.f, 0.f);
            cur = ed.z;
        }
        const float wv = __int_as_float(ed.y);
        const float4 v = __ldcg(reinterpret_cast<const float4*>(
                              h_in + (size_t)ed.x * EMB_DIM) + c);
        acc.x = fmaf(v.x, wv, acc.x);
        acc.y = fmaf(v.y, wv, acc.y);
        acc.z = fmaf(v.z, wv, acc.z);
        acc.w = fmaf(v.w, wv, acc.w);
    }
    float* p = h_out + (size_t)cur * EMB_DIM + (size_t)c * 4;
    asm volatile("red.global.add.v4.f32 [%0], {%1, %2, %3, %4};"
                 :: "l"(p), "f"(acc.x), "f"(acc.y), "f"(acc.z), "f"(acc.w));
}

// ---------------------------------------------------------------------------
// Launcher. Fork/join under graph capture: transform + ALL output zeroing on
// side stream, CSR build on legacy stream; join; 3 hops (no serial memsets).
// ---------------------------------------------------------------------------
extern "C" void kernel_launch(void* const* d_in, const int* in_sizes, int n_in,
                              void* d_out, int out_size)
{
    const float* x   = (const float*)d_in[0];
    const float* W   = (const float*)d_in[1];
    const float* b   = (const float*)d_in[2];
    const float* w   = (const float*)d_in[3];
    const int*   src = (const int*)d_in[4];
    const int*   dst = (const int*)d_in[5];
    float* out = (float*)d_out;

    const int n_nodes = in_sizes[0] / IN_DIM;
    const int n_edges = in_sizes[3];
    const size_t h_bytes = (size_t)n_nodes * EMB_DIM * sizeof(float);

    float* hA = nullptr; float* hB = nullptr; float* hC = nullptr; int* counts = nullptr;
    cudaGetSymbolAddress((void**)&hA, g_hA);
    cudaGetSymbolAddress((void**)&hB, g_hB);
    cudaGetSymbolAddress((void**)&hC, g_hC);
    cudaGetSymbolAddress((void**)&counts, g_counts);

    cudaStream_t s2;
    cudaEvent_t evFork, evJoin;
    cudaStreamCreateWithFlags(&s2, cudaStreamNonBlocking);
    cudaEventCreateWithFlags(&evFork, cudaEventDisableTiming);
    cudaEventCreateWithFlags(&evJoin, cudaEventDisableTiming);

    // Fork side stream off the capture-origin (legacy) stream.
    cudaEventRecord(evFork, 0);
    cudaStreamWaitEvent(s2, evFork, 0);

    // Branch A (s2): transform + zero all hop outputs.
    sgc_transform<<<(n_nodes + 255) / 256, 256, 0, s2>>>(x, W, b, hA, n_nodes);
    cudaMemsetAsync(hB, 0, h_bytes, s2);
    cudaMemsetAsync(hC, 0, h_bytes, s2);
    cudaMemsetAsync(out, 0, (size_t)out_size * sizeof(float), s2);

    // Branch B (legacy stream): CSR build.
    cudaMemsetAsync(counts, 0, (size_t)n_nodes * sizeof(int));
    csr_histogram<<<(n_edges / 8 + 255) / 256, 256>>>(dst, n_edges);
    const int scan_blocks = (n_nodes + SCAN_B - 1) / SCAN_B;
    csr_scan<<<scan_blocks, SCAN_B>>>(n_nodes);
    csr_scatter<<<(n_edges / 8 + 255) / 256, 256>>>(src, dst, w, n_edges);

    // Join.
    cudaEventRecord(evJoin, s2);
    cudaStreamWaitEvent(0, evJoin, 0);

    // 3 hops (legacy stream), no serial memsets.
    const long long n_grp = ((long long)n_edges + CHUNK - 1) / CHUNK;
    const int hop_blocks = (int)((n_grp * 8 + 255) / 256);

    sgc_hop_chunk<<<hop_blocks, 256>>>(hA, hB, n_edges);
    sgc_hop_chunk<<<hop_blocks, 256>>>(hB, hC, n_edges);
    sgc_hop_chunk<<<hop_blocks, 256>>>(hC, out, n_edges);
}